// round 10
// baseline (speedup 1.0000x reference)
#include <cuda_runtime.h>
#include <cstdint>

#define HW      262144          // 512*512 = 2^18
#define BSZ     64
#define CC      3
#define NU      (BSZ*HW)        // 16777216 uniforms (mask domain)
#define NX      (BSZ*CC*HW)     // 50331648 x elements
#define KKEEP   183500          // int(262144*0.7)
#define CAP     12288           // candidate capacity per row (expected ~8192)
#define SEG     32              // gen blocks per row
// Fixed selection window around expected k-th key (0.7 * 2^23 = 5872025.6;
// k/n*2^23 = 5872000). Rank sigma ~235 elems ~ 7500 key units; +-131072 = ~17 sigma.
#define T_LO    5740928u
#define T_HI    6003072u

// ---------------- static device scratch (no allocation allowed) -------------
__device__ uint32_t           g_m[NU];               // cached 23-bit uniform keys
__device__ uint32_t           g_below[BSZ];          // exact count of m < T_LO
__device__ unsigned long long g_pairs[BSZ][CAP];     // window candidates (m<<18|col)
__device__ uint32_t           g_cnt[BSZ];
__device__ uint32_t           g_thresh[BSZ];
__device__ uint32_t           g_tiecols[BSZ][64];
__device__ uint32_t           g_ntk[BSZ];

// ---------------- Threefry-2x32 (20 rounds), matches jax._src.prng ----------
#define TFR_S(r) { x0 += x1; x1 = ((x1 << (r)) | (x1 >> (32 - (r)))) ^ x0; }
#define TFR_I(r) { x0 += x1;                                                 \
                   unsigned long long _p = (unsigned long long)x1 *          \
                                           (uint32_t)(1u << (r));            \
                   x1 = ((uint32_t)_p | (uint32_t)(_p >> 32)) ^ x0; }

// all-IMAD rotations: integer-only callers (mask/key path)
__host__ __device__ __forceinline__
void tf2x32_i(uint32_t k0, uint32_t k1, uint32_t x0, uint32_t x1,
              uint32_t &o0, uint32_t &o1) {
    uint32_t ks2 = k0 ^ k1 ^ 0x1BD11BDAu;
    x0 += k0;  x1 += k1;
    TFR_I(13) TFR_I(15) TFR_I(26) TFR_I(6)
    x0 += k1;  x1 += ks2 + 1u;
    TFR_I(17) TFR_I(29) TFR_I(16) TFR_I(24)
    x0 += ks2; x1 += k0 + 2u;
    TFR_I(13) TFR_I(15) TFR_I(26) TFR_I(6)
    x0 += k0;  x1 += k1 + 3u;
    TFR_I(17) TFR_I(29) TFR_I(16) TFR_I(24)
    x0 += k1;  x1 += ks2 + 4u;
    TFR_I(13) TFR_I(15) TFR_I(26) TFR_I(6)
    x0 += ks2; x1 += k0 + 5u;
    o0 = x0; o1 = x1;
}

// mixed rotations (10 IMAD / 10 SHF): noise path (erfinv FFMAs load fma pipe)
__device__ __forceinline__
void tf2x32_m(uint32_t k0, uint32_t k1, uint32_t x0, uint32_t x1,
              uint32_t &o0, uint32_t &o1) {
    uint32_t ks2 = k0 ^ k1 ^ 0x1BD11BDAu;
    x0 += k0;  x1 += k1;
    TFR_I(13) TFR_S(15) TFR_I(26) TFR_S(6)
    x0 += k1;  x1 += ks2 + 1u;
    TFR_I(17) TFR_S(29) TFR_I(16) TFR_S(24)
    x0 += ks2; x1 += k0 + 2u;
    TFR_I(13) TFR_S(15) TFR_I(26) TFR_S(6)
    x0 += k0;  x1 += k1 + 3u;
    TFR_I(17) TFR_S(29) TFR_I(16) TFR_S(24)
    x0 += k1;  x1 += ks2 + 4u;
    TFR_I(13) TFR_S(15) TFR_I(26) TFR_S(6)
    x0 += ks2; x1 += k0 + 5u;
    o0 = x0; o1 = x1;
}

// jax_threefry_partitionable=True 32-bit random bits: ctr=(0,i), out = x0^x1
__device__ __forceinline__ uint32_t rbits32_i(uint32_t k0, uint32_t k1, uint32_t i) {
    uint32_t a, b;
    tf2x32_i(k0, k1, 0u, i, a, b);
    return a ^ b;
}
__device__ __forceinline__ uint32_t rbits32_m(uint32_t k0, uint32_t k1, uint32_t i) {
    uint32_t a, b;
    tf2x32_m(k0, k1, 0u, i, a, b);
    return a ^ b;
}

// XLA ErfInv (fp32, Giles polynomial)
__device__ __forceinline__ float erfinv_f(float x) {
    float w = -__logf((1.0f - x) * (1.0f + x));
    float p;
    if (w < 5.0f) {
        w -= 2.5f;
        p =               2.81022636e-08f;
        p = fmaf(p, w,    3.43273939e-07f);
        p = fmaf(p, w,   -3.5233877e-06f);
        p = fmaf(p, w,   -4.39150654e-06f);
        p = fmaf(p, w,    0.00021858087f);
        p = fmaf(p, w,   -0.00125372503f);
        p = fmaf(p, w,   -0.00417768164f);
        p = fmaf(p, w,    0.246640727f);
        p = fmaf(p, w,    1.50140941f);
    } else {
        w = sqrtf(w) - 3.0f;
        p =              -0.000200214257f;
        p = fmaf(p, w,    0.000100950558f);
        p = fmaf(p, w,    0.00134934322f);
        p = fmaf(p, w,   -0.00367342844f);
        p = fmaf(p, w,    0.00573950773f);
        p = fmaf(p, w,   -0.0076224613f);
        p = fmaf(p, w,    0.00943887047f);
        p = fmaf(p, w,    1.00167406f);
        p = fmaf(p, w,    2.83297682f);
    }
    return p * x;
}

// noise factor for element index gi: 1 + 0.1 * N(0,1)
__device__ __forceinline__ float noise_f(uint32_t nk0, uint32_t nk1, uint32_t gi) {
    uint32_t bits = rbits32_m(nk0, nk1, gi);
    float f = __uint_as_float((bits >> 9) | 0x3F800000u) - 1.0f;
    float u = f * 2.0f + (-0.99999994f);      // lo = nextafter(-1,0), hi-lo = 2
    u = fmaxf(u, -0.99999994f);
    float nrm = 1.4142135623730951f * erfinv_f(u);
    return fmaf(nrm, 0.1f, 1.0f);
}

// ---------------- kernels ----------------------------------------------------
__global__ void k_init() {
    uint32_t i = threadIdx.x;
    if (i < BSZ) { g_cnt[i] = 0u; g_ntk[i] = 0u; g_below[i] = 0u; }
}

// Generate keys, cache m=bits>>9, exact count below T_LO (warp-aggregated),
// append window candidates. NO per-element histogram atomics.
__global__ void __launch_bounds__(256)
k_gen(uint32_t mk0, uint32_t mk1) {
    uint32_t row  = blockIdx.x / SEG;
    uint32_t seg  = blockIdx.x % SEG;
    uint32_t base = row * HW + seg * (HW / SEG);
    uint32_t cntlo = 0;
#pragma unroll 8
    for (int it = 0; it < (HW / SEG) / 256; it++) {
        uint32_t i = base + it * 256 + threadIdx.x;
        uint32_t m = rbits32_i(mk0, mk1, i) >> 9;
        g_m[i] = m;
        cntlo += (m < T_LO) ? 1u : 0u;
        if (m >= T_LO && m < T_HI) {
            uint32_t pos = atomicAdd(&g_cnt[row], 1u);
            if (pos < CAP)
                g_pairs[row][pos] =
                    (((unsigned long long)m) << 18) | (i & 0x3FFFFu);
        }
    }
    // warp reduce + one atomic per warp
    cntlo += __shfl_xor_sync(0xffffffffu, cntlo, 16);
    cntlo += __shfl_xor_sync(0xffffffffu, cntlo, 8);
    cntlo += __shfl_xor_sync(0xffffffffu, cntlo, 4);
    cntlo += __shfl_xor_sync(0xffffffffu, cntlo, 2);
    cntlo += __shfl_xor_sync(0xffffffffu, cntlo, 1);
    if ((threadIdx.x & 31u) == 0u) atomicAdd(&g_below[row], cntlo);
}

// One block per row: exact k-th key + stable (index-ordered) tie set,
// via 1024-bucket mini-histogram over the ~8192 window candidates.
__global__ void __launch_bounds__(256)
k_sel() {
    int row = blockIdx.x;
    __shared__ uint32_t hist2[1024];
    __shared__ unsigned long long sp2[256];
    __shared__ uint32_t sn2, sB2, sR2, sT;
    for (int j = threadIdx.x; j < 1024; j += 256) hist2[j] = 0u;
    if (threadIdx.x == 0) sn2 = 0u;
    __syncthreads();

    uint32_t n = min(g_cnt[row], (uint32_t)CAP);
    for (uint32_t j = threadIdx.x; j < n; j += 256) {
        uint32_t m = (uint32_t)(g_pairs[row][j] >> 18);
        atomicAdd(&hist2[(m - T_LO) >> 8], 1u);
    }
    __syncthreads();

    if (threadIdx.x == 0) {
        uint32_t r = (uint32_t)KKEEP - g_below[row];  // 1-indexed rank among candidates
        uint32_t cum = 0, B2 = 0;
        for (int b = 0; b < 1024; b++) {
            uint32_t h = hist2[b];
            if (cum + h >= r) { B2 = (uint32_t)b; break; }
            cum += h;
        }
        sB2 = B2; sR2 = r - cum;                      // 1-indexed within bucket
    }
    __syncthreads();

    uint32_t B2 = sB2, r2 = sR2;
    for (uint32_t j = threadIdx.x; j < n; j += 256) {
        unsigned long long v = g_pairs[row][j];
        uint32_t m = (uint32_t)(v >> 18);
        if (((m - T_LO) >> 8) == B2) {
            uint32_t pos = atomicAdd(&sn2, 1u);
            if (pos < 256u) sp2[pos] = v;
        }
    }
    __syncthreads();

    uint32_t n2 = min(sn2, 256u);
    for (uint32_t j = threadIdx.x; j < n2; j += 256) {
        unsigned long long v = sp2[j];
        uint32_t rk = 0;
        for (uint32_t l = 0; l < n2; l++) rk += (sp2[l] < v) ? 1u : 0u;
        if (rk == r2 - 1u) sT = (uint32_t)(v >> 18);
    }
    __syncthreads();

    uint32_t T = sT;
    if (threadIdx.x == 0) g_thresh[row] = T;
    for (uint32_t j = threadIdx.x; j < n2; j += 256) {
        unsigned long long v = sp2[j];
        if ((uint32_t)(v >> 18) == T) {
            uint32_t rk = 0;
            for (uint32_t l = 0; l < n2; l++) rk += (sp2[l] < v) ? 1u : 0u;
            if (rk < r2) {
                uint32_t pos = atomicAdd(&g_ntk[row], 1u);
                if (pos < 64u) g_tiecols[row][pos] = (uint32_t)(v & 0x3FFFFu);
            }
        }
    }
}

// Fused: per pixel-quad -> mask (write) + all 3 channels of out
__global__ void __launch_bounds__(256)
k_out_fused(const float4* __restrict__ x, float4* __restrict__ out,
            float4* __restrict__ maskout, uint32_t nk0, uint32_t nk1) {
    uint32_t q   = blockIdx.x * blockDim.x + threadIdx.x;  // [0, NU/4)
    uint32_t pix = q * 4u;
    uint32_t b   = pix >> 18;
    uint32_t p   = pix & 0x3FFFFu;
    uint32_t T   = g_thresh[b];

    uint4 mq = reinterpret_cast<const uint4*>(g_m)[q];
    uint32_t ms[4] = {mq.x, mq.y, mq.z, mq.w};
    float mk[4];
    bool anytie = (ms[0] == T) | (ms[1] == T) | (ms[2] == T) | (ms[3] == T);
#pragma unroll
    for (int j = 0; j < 4; j++) mk[j] = (ms[j] < T) ? 1.0f : 0.0f;
    if (anytie) {
        uint32_t ntk = g_ntk[b];
#pragma unroll
        for (int j = 0; j < 4; j++) {
            if (ms[j] == T) {
                uint32_t col = p + (uint32_t)j;
                for (uint32_t t = 0; t < ntk; t++)
                    if (g_tiecols[b][t] == col) mk[j] = 1.0f;
            }
        }
    }
    maskout[q] = make_float4(mk[0], mk[1], mk[2], mk[3]);

    uint32_t gibase = (b * 3u) * (uint32_t)HW + p;   // channel 0 element index
#pragma unroll
    for (int c = 0; c < 3; c++) {
        uint32_t gi = gibase + (uint32_t)c * (uint32_t)HW;
        float4 xv = x[gi >> 2];
        float n0 = noise_f(nk0, nk1, gi + 0u);
        float n1 = noise_f(nk0, nk1, gi + 1u);
        float n2 = noise_f(nk0, nk1, gi + 2u);
        float n3 = noise_f(nk0, nk1, gi + 3u);
        float4 o;
        o.x = xv.x * mk[0] * n0;
        o.y = xv.y * mk[1] * n1;
        o.z = xv.z * mk[2] * n2;
        o.w = xv.w * mk[3] * n3;
        out[gi >> 2] = o;
    }
}

// ---------------- launch ------------------------------------------------------
extern "C" void kernel_launch(void* const* d_in, const int* in_sizes, int n_in,
                              void* d_out, int out_size) {
    const float* x   = (const float*)d_in[0];
    float* out       = (float*)d_out;
    float* maskout   = out + NX;          // output layout: [x (NX) | mask (NU)]

    // jax.random.key(42) -> (0,42); partitionable fold-like split:
    uint32_t mk0, mk1, nk0, nk1;
    tf2x32_i(0u, 42u, 0u, 0u, mk0, mk1);    // k_mask
    tf2x32_i(0u, 42u, 0u, 1u, nk0, nk1);    // k_noise

    k_init     <<<1, 64>>>();
    k_gen      <<<BSZ * SEG, 256>>>(mk0, mk1);
    k_sel      <<<BSZ, 256>>>();
    k_out_fused<<<(NU / 4) / 256, 256>>>((const float4*)x, (float4*)out,
                                         (float4*)maskout, nk0, nk1);
}

// round 11
// speedup vs baseline: 1.8925x; 1.8925x over previous
#include <cuda_runtime.h>
#include <cstdint>

#define HW      262144          // 512*512 = 2^18
#define BSZ     64
#define CC      3
#define NU      (BSZ*HW)        // 16777216 uniforms (mask domain)
#define NX      (BSZ*CC*HW)     // 50331648 x elements
#define KKEEP   183500          // int(262144*0.7)
#define CAP     12288           // candidate capacity per row (expected ~8192)
#define SEG     32              // gen blocks per row
#define SBUF    640             // per-block staging (expected 256, ~24 sigma)
// Fixed selection window around expected k-th key (0.7*2^23 ~ 5872026).
// Rank sigma ~235 elems ~ 7500 key units; +-131072 ~ 17 sigma.
#define T_LO    5740928u
#define T_HI    6003072u

// ---------------- static device scratch (no allocation allowed) -------------
__device__ uint32_t           g_m[NU];               // cached 23-bit uniform keys
__device__ uint32_t           g_below[BSZ];          // exact count of m < T_LO
__device__ unsigned long long g_pairs[BSZ][CAP];     // window candidates (m<<18|col)
__device__ uint32_t           g_cnt[BSZ];
__device__ uint32_t           g_thresh[BSZ];
__device__ uint32_t           g_tiecols[BSZ][64];
__device__ uint32_t           g_ntk[BSZ];

// ---------------- Threefry-2x32 (20 rounds), matches jax._src.prng ----------
// rotIM: rotate via 32x32->64 multiply by runtime-opaque 2^r (kernel arg) ->
//        IMAD.WIDE on the fma pipe + one LOP3 for (lo|hi)^x0.
// TFS:   funnel rotate (SHF.L.W) + LOP3, both alu pipe.
__device__ __forceinline__ uint32_t rotIM(uint32_t v, uint32_t pw) {
    unsigned long long p = (unsigned long long)v * pw;   // pw = 2^r (opaque)
    return (uint32_t)p | (uint32_t)(p >> 32);
}
#define TFI(pw) { x0 += x1; x1 = rotIM(x1, (pw)) ^ x0; }
#define TFS(r)  { x0 += x1; x1 = ((x1 << (r)) | (x1 >> (32 - (r)))) ^ x0; }

// host/compile-time reference version (for key derivation on host)
__host__ __device__ __forceinline__
void tf2x32_h(uint32_t k0, uint32_t k1, uint32_t x0, uint32_t x1,
              uint32_t &o0, uint32_t &o1) {
    uint32_t ks2 = k0 ^ k1 ^ 0x1BD11BDAu;
#define TFRH(r) { x0 += x1; x1 = ((x1 << (r)) | (x1 >> (32 - (r)))) ^ x0; }
    x0 += k0;  x1 += k1;
    TFRH(13) TFRH(15) TFRH(26) TFRH(6)
    x0 += k1;  x1 += ks2 + 1u;
    TFRH(17) TFRH(29) TFRH(16) TFRH(24)
    x0 += ks2; x1 += k0 + 2u;
    TFRH(13) TFRH(15) TFRH(26) TFRH(6)
    x0 += k0;  x1 += k1 + 3u;
    TFRH(17) TFRH(29) TFRH(16) TFRH(24)
    x0 += k1;  x1 += ks2 + 4u;
    TFRH(13) TFRH(15) TFRH(26) TFRH(6)
    x0 += ks2; x1 += k0 + 5u;
#undef TFRH
    o0 = x0; o1 = x1;
}

// all-IMAD rotations (integer-only kernels: key/mask path)
// pw0 = {2^13,2^15,2^26,2^6}, pw1 = {2^17,2^29,2^16,2^24}
__device__ __forceinline__
uint32_t rbits_gen(uint32_t k0, uint32_t k1, uint32_t i,
                   uint4 pw0, uint4 pw1) {
    uint32_t ks2 = k0 ^ k1 ^ 0x1BD11BDAu;
    uint32_t x0 = k0, x1 = i + k1;
    TFI(pw0.x) TFI(pw0.y) TFI(pw0.z) TFI(pw0.w)
    x0 += k1;  x1 += ks2 + 1u;
    TFI(pw1.x) TFI(pw1.y) TFI(pw1.z) TFI(pw1.w)
    x0 += ks2; x1 += k0 + 2u;
    TFI(pw0.x) TFI(pw0.y) TFI(pw0.z) TFI(pw0.w)
    x0 += k0;  x1 += k1 + 3u;
    TFI(pw1.x) TFI(pw1.y) TFI(pw1.z) TFI(pw1.w)
    x0 += k1;  x1 += ks2 + 4u;
    TFI(pw0.x) TFI(pw0.y) TFI(pw0.z) TFI(pw0.w)
    x0 += ks2; x1 += k0 + 5u;
    return x0 ^ x1;
}

// mixed rotations (10 IMAD / 10 funnel-SHF) for the noise path
__device__ __forceinline__
uint32_t rbits_noise(uint32_t k0, uint32_t k1, uint32_t i,
                     uint4 pw0, uint4 pw1) {
    uint32_t ks2 = k0 ^ k1 ^ 0x1BD11BDAu;
    uint32_t x0 = k0, x1 = i + k1;
    TFI(pw0.x) TFS(15) TFI(pw0.z) TFS(6)
    x0 += k1;  x1 += ks2 + 1u;
    TFI(pw1.x) TFS(29) TFI(pw1.z) TFS(24)
    x0 += ks2; x1 += k0 + 2u;
    TFI(pw0.x) TFS(15) TFI(pw0.z) TFS(6)
    x0 += k0;  x1 += k1 + 3u;
    TFI(pw1.x) TFS(29) TFI(pw1.z) TFS(24)
    x0 += k1;  x1 += ks2 + 4u;
    TFI(pw0.x) TFS(15) TFI(pw0.z) TFS(6)
    x0 += ks2; x1 += k0 + 5u;
    return x0 ^ x1;
}

// XLA ErfInv (fp32, Giles polynomial)
__device__ __forceinline__ float erfinv_f(float x) {
    float w = -__logf((1.0f - x) * (1.0f + x));
    float p;
    if (w < 5.0f) {
        w -= 2.5f;
        p =               2.81022636e-08f;
        p = fmaf(p, w,    3.43273939e-07f);
        p = fmaf(p, w,   -3.5233877e-06f);
        p = fmaf(p, w,   -4.39150654e-06f);
        p = fmaf(p, w,    0.00021858087f);
        p = fmaf(p, w,   -0.00125372503f);
        p = fmaf(p, w,   -0.00417768164f);
        p = fmaf(p, w,    0.246640727f);
        p = fmaf(p, w,    1.50140941f);
    } else {
        w = sqrtf(w) - 3.0f;
        p =              -0.000200214257f;
        p = fmaf(p, w,    0.000100950558f);
        p = fmaf(p, w,    0.00134934322f);
        p = fmaf(p, w,   -0.00367342844f);
        p = fmaf(p, w,    0.00573950773f);
        p = fmaf(p, w,   -0.0076224613f);
        p = fmaf(p, w,    0.00943887047f);
        p = fmaf(p, w,    1.00167406f);
        p = fmaf(p, w,    2.83297682f);
    }
    return p * x;
}

// noise factor for element index gi: 1 + 0.1 * N(0,1)
__device__ __forceinline__ float noise_f(uint32_t nk0, uint32_t nk1, uint32_t gi,
                                         uint4 pw0, uint4 pw1) {
    uint32_t bits = rbits_noise(nk0, nk1, gi, pw0, pw1);
    float f = __uint_as_float((bits >> 9) | 0x3F800000u) - 1.0f;
    float u = f * 2.0f + (-0.99999994f);      // lo = nextafter(-1,0), hi-lo = 2
    u = fmaxf(u, -0.99999994f);
    float nrm = 1.4142135623730951f * erfinv_f(u);
    return fmaf(nrm, 0.1f, 1.0f);
}

// ---------------- kernels ----------------------------------------------------
__global__ void k_init() {
    uint32_t i = threadIdx.x;
    if (i < BSZ) { g_cnt[i] = 0u; g_ntk[i] = 0u; g_below[i] = 0u; }
}

// Generate keys, cache m=bits>>9, exact count of m<T_LO (warp-aggregated),
// window candidates staged in SHARED, one global atomic per block.
__global__ void __launch_bounds__(256)
k_gen(uint32_t mk0, uint32_t mk1, uint4 pw0, uint4 pw1) {
    __shared__ unsigned long long s_buf[SBUF];
    __shared__ uint32_t s_cnt;
    __shared__ uint32_t s_base;
    if (threadIdx.x == 0) s_cnt = 0u;
    __syncthreads();

    uint32_t row  = blockIdx.x / SEG;
    uint32_t seg  = blockIdx.x % SEG;
    uint32_t base = row * HW + seg * (HW / SEG);
    uint32_t cntlo = 0;
#pragma unroll 8
    for (int it = 0; it < (HW / SEG) / 256; it++) {
        uint32_t i = base + it * 256 + threadIdx.x;
        uint32_t m = rbits_gen(mk0, mk1, i, pw0, pw1) >> 9;
        g_m[i] = m;
        cntlo += (m < T_LO) ? 1u : 0u;
        if (m >= T_LO && m < T_HI) {
            uint32_t pos = atomicAdd(&s_cnt, 1u);
            if (pos < SBUF)
                s_buf[pos] = (((unsigned long long)m) << 18) | (i & 0x3FFFFu);
        }
    }
    // warp reduce + one atomic per warp (below-window exact count)
    cntlo += __shfl_xor_sync(0xffffffffu, cntlo, 16);
    cntlo += __shfl_xor_sync(0xffffffffu, cntlo, 8);
    cntlo += __shfl_xor_sync(0xffffffffu, cntlo, 4);
    cntlo += __shfl_xor_sync(0xffffffffu, cntlo, 2);
    cntlo += __shfl_xor_sync(0xffffffffu, cntlo, 1);
    if ((threadIdx.x & 31u) == 0u) atomicAdd(&g_below[row], cntlo);

    __syncthreads();
    uint32_t n = min(s_cnt, (uint32_t)SBUF);
    if (threadIdx.x == 0) s_base = atomicAdd(&g_cnt[row], n);
    __syncthreads();
    uint32_t gb = s_base;
    for (uint32_t j = threadIdx.x; j < n; j += 256)
        if (gb + j < CAP) g_pairs[row][gb + j] = s_buf[j];
}

// One block per row: exact k-th key + stable (index-ordered) tie set,
// via 1024-bucket mini-histogram over the ~8192 window candidates.
__global__ void __launch_bounds__(256)
k_sel() {
    int row = blockIdx.x;
    __shared__ uint32_t hist2[1024];
    __shared__ unsigned long long sp2[256];
    __shared__ uint32_t sn2, sB2, sR2, sT;
    for (int j = threadIdx.x; j < 1024; j += 256) hist2[j] = 0u;
    if (threadIdx.x == 0) sn2 = 0u;
    __syncthreads();

    uint32_t n = min(g_cnt[row], (uint32_t)CAP);
    for (uint32_t j = threadIdx.x; j < n; j += 256) {
        uint32_t m = (uint32_t)(g_pairs[row][j] >> 18);
        atomicAdd(&hist2[(m - T_LO) >> 8], 1u);
    }
    __syncthreads();

    if (threadIdx.x == 0) {
        uint32_t r = (uint32_t)KKEEP - g_below[row];  // 1-indexed rank among candidates
        uint32_t cum = 0, B2 = 0;
        for (int b = 0; b < 1024; b++) {
            uint32_t h = hist2[b];
            if (cum + h >= r) { B2 = (uint32_t)b; break; }
            cum += h;
        }
        sB2 = B2; sR2 = r - cum;                      // 1-indexed within bucket
    }
    __syncthreads();

    uint32_t B2 = sB2, r2 = sR2;
    for (uint32_t j = threadIdx.x; j < n; j += 256) {
        unsigned long long v = g_pairs[row][j];
        uint32_t m = (uint32_t)(v >> 18);
        if (((m - T_LO) >> 8) == B2) {
            uint32_t pos = atomicAdd(&sn2, 1u);
            if (pos < 256u) sp2[pos] = v;
        }
    }
    __syncthreads();

    uint32_t n2 = min(sn2, 256u);
    for (uint32_t j = threadIdx.x; j < n2; j += 256) {
        unsigned long long v = sp2[j];
        uint32_t rk = 0;
        for (uint32_t l = 0; l < n2; l++) rk += (sp2[l] < v) ? 1u : 0u;
        if (rk == r2 - 1u) sT = (uint32_t)(v >> 18);
    }
    __syncthreads();

    uint32_t T = sT;
    if (threadIdx.x == 0) g_thresh[row] = T;
    for (uint32_t j = threadIdx.x; j < n2; j += 256) {
        unsigned long long v = sp2[j];
        if ((uint32_t)(v >> 18) == T) {
            uint32_t rk = 0;
            for (uint32_t l = 0; l < n2; l++) rk += (sp2[l] < v) ? 1u : 0u;
            if (rk < r2) {
                uint32_t pos = atomicAdd(&g_ntk[row], 1u);
                if (pos < 64u) g_tiecols[row][pos] = (uint32_t)(v & 0x3FFFFu);
            }
        }
    }
}

// Fused: per pixel-quad -> mask (write) + all 3 channels of out
__global__ void __launch_bounds__(256)
k_out_fused(const float4* __restrict__ x, float4* __restrict__ out,
            float4* __restrict__ maskout, uint32_t nk0, uint32_t nk1,
            uint4 pw0, uint4 pw1) {
    uint32_t q   = blockIdx.x * blockDim.x + threadIdx.x;  // [0, NU/4)
    uint32_t pix = q * 4u;
    uint32_t b   = pix >> 18;
    uint32_t p   = pix & 0x3FFFFu;
    uint32_t T   = g_thresh[b];

    uint4 mq = reinterpret_cast<const uint4*>(g_m)[q];
    uint32_t ms[4] = {mq.x, mq.y, mq.z, mq.w};
    float mk[4];
    bool anytie = (ms[0] == T) | (ms[1] == T) | (ms[2] == T) | (ms[3] == T);
#pragma unroll
    for (int j = 0; j < 4; j++) mk[j] = (ms[j] < T) ? 1.0f : 0.0f;
    if (anytie) {
        uint32_t ntk = g_ntk[b];
#pragma unroll
        for (int j = 0; j < 4; j++) {
            if (ms[j] == T) {
                uint32_t col = p + (uint32_t)j;
                for (uint32_t t = 0; t < ntk; t++)
                    if (g_tiecols[b][t] == col) mk[j] = 1.0f;
            }
        }
    }
    maskout[q] = make_float4(mk[0], mk[1], mk[2], mk[3]);

    uint32_t gibase = (b * 3u) * (uint32_t)HW + p;   // channel 0 element index
#pragma unroll
    for (int c = 0; c < 3; c++) {
        uint32_t gi = gibase + (uint32_t)c * (uint32_t)HW;
        float4 xv = x[gi >> 2];
        float n0 = noise_f(nk0, nk1, gi + 0u, pw0, pw1);
        float n1 = noise_f(nk0, nk1, gi + 1u, pw0, pw1);
        float n2 = noise_f(nk0, nk1, gi + 2u, pw0, pw1);
        float n3 = noise_f(nk0, nk1, gi + 3u, pw0, pw1);
        float4 o;
        o.x = xv.x * mk[0] * n0;
        o.y = xv.y * mk[1] * n1;
        o.z = xv.z * mk[2] * n2;
        o.w = xv.w * mk[3] * n3;
        out[gi >> 2] = o;
    }
}

// ---------------- launch ------------------------------------------------------
extern "C" void kernel_launch(void* const* d_in, const int* in_sizes, int n_in,
                              void* d_out, int out_size) {
    const float* x   = (const float*)d_in[0];
    float* out       = (float*)d_out;
    float* maskout   = out + NX;          // output layout: [x (NX) | mask (NU)]

    // jax.random.key(42) -> (0,42); partitionable fold-like split:
    uint32_t mk0, mk1, nk0, nk1;
    tf2x32_h(0u, 42u, 0u, 0u, mk0, mk1);    // k_mask
    tf2x32_h(0u, 42u, 0u, 1u, nk0, nk1);    // k_noise

    // rotation powers, passed as runtime args so ptxas emits IMAD.WIDE
    uint4 pw0 = make_uint4(1u << 13, 1u << 15, 1u << 26, 1u << 6);
    uint4 pw1 = make_uint4(1u << 17, 1u << 29, 1u << 16, 1u << 24);

    k_init     <<<1, 64>>>();
    k_gen      <<<BSZ * SEG, 256>>>(mk0, mk1, pw0, pw1);
    k_sel      <<<BSZ, 256>>>();
    k_out_fused<<<(NU / 4) / 256, 256>>>((const float4*)x, (float4*)out,
                                         (float4*)maskout, nk0, nk1, pw0, pw1);
}

// round 15
// speedup vs baseline: 1.9834x; 1.0480x over previous
#include <cuda_runtime.h>
#include <cstdint>

#define HW      262144          // 512*512 = 2^18
#define BSZ     64
#define CC      3
#define NU      (BSZ*HW)        // 16777216 uniforms (mask domain)
#define NX      (BSZ*CC*HW)     // 50331648 x elements
#define KKEEP   183500          // int(262144*0.7)
#define CAP     12288           // candidate capacity per row (expected ~8192)
#define SEG     32              // gen blocks per row
#define SBUF    640             // per-block staging (expected 256, ~24 sigma)
// Fixed selection window around expected k-th key (0.7*2^23 ~ 5872026).
// Rank sigma ~235 elems ~ 7500 key units; +-131072 ~ 17 sigma.
#define T_LO    5740928u
#define T_HI    6003072u

// ---------------- static device scratch (no allocation allowed) -------------
__device__ uint32_t           g_m[NU];               // cached 23-bit uniform keys
__device__ uint32_t           g_below[BSZ];          // exact count of m < T_LO
__device__ unsigned long long g_pairs[BSZ][CAP];     // window candidates (m<<18|col)
__device__ uint32_t           g_cnt[BSZ];
__device__ uint32_t           g_thresh[BSZ];
__device__ uint32_t           g_tiecols[BSZ][64];
__device__ uint32_t           g_ntk[BSZ];

// ---------------- Threefry-2x32 (20 rounds), matches jax._src.prng ----------
// rotIM: rotate via 32x32->64 multiply by runtime-opaque 2^r (kernel arg) ->
//        IMAD.WIDE on the fma pipe + one LOP3 for (lo|hi)^x0.
__device__ __forceinline__ uint32_t rotIM(uint32_t v, uint32_t pw) {
    unsigned long long p = (unsigned long long)v * pw;   // pw = 2^r (opaque)
    return (uint32_t)p | (uint32_t)(p >> 32);
}

// host reference version (key derivation on host)
__host__ __device__ __forceinline__
void tf2x32_h(uint32_t k0, uint32_t k1, uint32_t x0, uint32_t x1,
              uint32_t &o0, uint32_t &o1) {
    uint32_t ks2 = k0 ^ k1 ^ 0x1BD11BDAu;
#define TFRH(r) { x0 += x1; x1 = ((x1 << (r)) | (x1 >> (32 - (r)))) ^ x0; }
    x0 += k0;  x1 += k1;
    TFRH(13) TFRH(15) TFRH(26) TFRH(6)
    x0 += k1;  x1 += ks2 + 1u;
    TFRH(17) TFRH(29) TFRH(16) TFRH(24)
    x0 += ks2; x1 += k0 + 2u;
    TFRH(13) TFRH(15) TFRH(26) TFRH(6)
    x0 += k0;  x1 += k1 + 3u;
    TFRH(17) TFRH(29) TFRH(16) TFRH(24)
    x0 += k1;  x1 += ks2 + 4u;
    TFRH(13) TFRH(15) TFRH(26) TFRH(6)
    x0 += ks2; x1 += k0 + 5u;
#undef TFRH
    o0 = x0; o1 = x1;
}

// 2-way interleaved round macros (A/B independent chains -> 2x ILP)
#define R2I(pw) { xA0 += xA1; xB0 += xB1;                                   \
                  xA1 = rotIM(xA1,(pw)) ^ xA0;                              \
                  xB1 = rotIM(xB1,(pw)) ^ xB0; }
#define R2S(r)  { xA0 += xA1; xB0 += xB1;                                   \
                  xA1 = ((xA1<<(r))|(xA1>>(32-(r)))) ^ xA0;                 \
                  xB1 = ((xB1<<(r))|(xB1>>(32-(r)))) ^ xB0; }
#define K2(a,b) { xA0 += (a); xA1 += (b); xB0 += (a); xB1 += (b); }

// 2-way all-IMAD rotations (integer-only key path)
__device__ __forceinline__
void rbits2_gen(uint32_t k0, uint32_t k1, uint32_t ks2,
                uint32_t iA, uint32_t iB, uint4 pw0, uint4 pw1,
                uint32_t &oA, uint32_t &oB) {
    uint32_t xA0 = k0, xA1 = iA + k1;
    uint32_t xB0 = k0, xB1 = iB + k1;
    R2I(pw0.x) R2I(pw0.y) R2I(pw0.z) R2I(pw0.w)
    K2(k1, ks2 + 1u)
    R2I(pw1.x) R2I(pw1.y) R2I(pw1.z) R2I(pw1.w)
    K2(ks2, k0 + 2u)
    R2I(pw0.x) R2I(pw0.y) R2I(pw0.z) R2I(pw0.w)
    K2(k0, k1 + 3u)
    R2I(pw1.x) R2I(pw1.y) R2I(pw1.z) R2I(pw1.w)
    K2(k1, ks2 + 4u)
    R2I(pw0.x) R2I(pw0.y) R2I(pw0.z) R2I(pw0.w)
    K2(ks2, k0 + 5u)
    oA = xA0 ^ xA1; oB = xB0 ^ xB1;
}

// 2-way mixed rotations (10 IMAD / 10 funnel-SHF) for the noise path
__device__ __forceinline__
void rbits2_noise(uint32_t k0, uint32_t k1, uint32_t ks2,
                  uint32_t iA, uint32_t iB, uint4 pw0, uint4 pw1,
                  uint32_t &oA, uint32_t &oB) {
    uint32_t xA0 = k0, xA1 = iA + k1;
    uint32_t xB0 = k0, xB1 = iB + k1;
    R2I(pw0.x) R2S(15) R2I(pw0.z) R2S(6)
    K2(k1, ks2 + 1u)
    R2I(pw1.x) R2S(29) R2I(pw1.z) R2S(24)
    K2(ks2, k0 + 2u)
    R2I(pw0.x) R2S(15) R2I(pw0.z) R2S(6)
    K2(k0, k1 + 3u)
    R2I(pw1.x) R2S(29) R2I(pw1.z) R2S(24)
    K2(k1, ks2 + 4u)
    R2I(pw0.x) R2S(15) R2I(pw0.z) R2S(6)
    K2(ks2, k0 + 5u)
    oA = xA0 ^ xA1; oB = xB0 ^ xB1;
}

// XLA ErfInv (fp32, Giles polynomial)
__device__ __forceinline__ float erfinv_f(float x) {
    float w = -__logf((1.0f - x) * (1.0f + x));
    float p;
    if (w < 5.0f) {
        w -= 2.5f;
        p =               2.81022636e-08f;
        p = fmaf(p, w,    3.43273939e-07f);
        p = fmaf(p, w,   -3.5233877e-06f);
        p = fmaf(p, w,   -4.39150654e-06f);
        p = fmaf(p, w,    0.00021858087f);
        p = fmaf(p, w,   -0.00125372503f);
        p = fmaf(p, w,   -0.00417768164f);
        p = fmaf(p, w,    0.246640727f);
        p = fmaf(p, w,    1.50140941f);
    } else {
        w = sqrtf(w) - 3.0f;
        p =              -0.000200214257f;
        p = fmaf(p, w,    0.000100950558f);
        p = fmaf(p, w,    0.00134934322f);
        p = fmaf(p, w,   -0.00367342844f);
        p = fmaf(p, w,    0.00573950773f);
        p = fmaf(p, w,   -0.0076224613f);
        p = fmaf(p, w,    0.00943887047f);
        p = fmaf(p, w,    1.00167406f);
        p = fmaf(p, w,    2.83297682f);
    }
    return p * x;
}

// two noise factors (1 + 0.1*N(0,1)) with interleaved threefry chains
__device__ __forceinline__
void noise2_f(uint32_t nk0, uint32_t nk1, uint32_t ks2,
              uint32_t iA, uint32_t iB, uint4 pw0, uint4 pw1,
              float &oA, float &oB) {
    uint32_t bA, bB;
    rbits2_noise(nk0, nk1, ks2, iA, iB, pw0, pw1, bA, bB);
    float fA = __uint_as_float((bA >> 9) | 0x3F800000u) - 1.0f;
    float fB = __uint_as_float((bB >> 9) | 0x3F800000u) - 1.0f;
    float uA = fmaxf(fA * 2.0f + (-0.99999994f), -0.99999994f);
    float uB = fmaxf(fB * 2.0f + (-0.99999994f), -0.99999994f);
    float nA = 1.4142135623730951f * erfinv_f(uA);
    float nB = 1.4142135623730951f * erfinv_f(uB);
    oA = fmaf(nA, 0.1f, 1.0f);
    oB = fmaf(nB, 0.1f, 1.0f);
}

// ---------------- kernels ----------------------------------------------------
__global__ void k_init() {
    uint32_t i = threadIdx.x;
    if (i < BSZ) { g_cnt[i] = 0u; g_ntk[i] = 0u; g_below[i] = 0u; }
}

// Generate keys (2-way ILP), cache m=bits>>9, exact count of m<T_LO,
// window candidates staged in SHARED, one global atomic per block.
__global__ void __launch_bounds__(256)
k_gen(uint32_t mk0, uint32_t mk1, uint4 pw0, uint4 pw1) {
    __shared__ unsigned long long s_buf[SBUF];
    __shared__ uint32_t s_cnt;
    __shared__ uint32_t s_base;
    if (threadIdx.x == 0) s_cnt = 0u;
    __syncthreads();

    uint32_t ks2  = mk0 ^ mk1 ^ 0x1BD11BDAu;
    uint32_t row  = blockIdx.x / SEG;
    uint32_t seg  = blockIdx.x % SEG;
    uint32_t base = row * HW + seg * (HW / SEG);
    uint32_t cntlo = 0;
#pragma unroll 4
    for (int it = 0; it < (HW / SEG) / 512; it++) {
        uint32_t iA = base + it * 512 + threadIdx.x;
        uint32_t iB = iA + 256u;
        uint32_t rA, rB;
        rbits2_gen(mk0, mk1, ks2, iA, iB, pw0, pw1, rA, rB);
        uint32_t mA = rA >> 9, mB = rB >> 9;
        g_m[iA] = mA;
        g_m[iB] = mB;
        cntlo += (mA < T_LO) ? 1u : 0u;
        cntlo += (mB < T_LO) ? 1u : 0u;
        if (mA >= T_LO && mA < T_HI) {
            uint32_t pos = atomicAdd(&s_cnt, 1u);
            if (pos < SBUF)
                s_buf[pos] = (((unsigned long long)mA) << 18) | (iA & 0x3FFFFu);
        }
        if (mB >= T_LO && mB < T_HI) {
            uint32_t pos = atomicAdd(&s_cnt, 1u);
            if (pos < SBUF)
                s_buf[pos] = (((unsigned long long)mB) << 18) | (iB & 0x3FFFFu);
        }
    }
    // warp reduce + one atomic per warp (below-window exact count)
    cntlo += __shfl_xor_sync(0xffffffffu, cntlo, 16);
    cntlo += __shfl_xor_sync(0xffffffffu, cntlo, 8);
    cntlo += __shfl_xor_sync(0xffffffffu, cntlo, 4);
    cntlo += __shfl_xor_sync(0xffffffffu, cntlo, 2);
    cntlo += __shfl_xor_sync(0xffffffffu, cntlo, 1);
    if ((threadIdx.x & 31u) == 0u) atomicAdd(&g_below[row], cntlo);

    __syncthreads();
    uint32_t n = min(s_cnt, (uint32_t)SBUF);
    if (threadIdx.x == 0) s_base = atomicAdd(&g_cnt[row], n);
    __syncthreads();
    uint32_t gb = s_base;
    for (uint32_t j = threadIdx.x; j < n; j += 256)
        if (gb + j < CAP) g_pairs[row][gb + j] = s_buf[j];
}

// One block per row: exact k-th key + stable (index-ordered) tie set,
// via 1024-bucket mini-histogram over the ~8192 window candidates.
__global__ void __launch_bounds__(256)
k_sel() {
    int row = blockIdx.x;
    __shared__ uint32_t hist2[1024];
    __shared__ unsigned long long sp2[256];
    __shared__ uint32_t sn2, sB2, sR2, sT;
    for (int j = threadIdx.x; j < 1024; j += 256) hist2[j] = 0u;
    if (threadIdx.x == 0) sn2 = 0u;
    __syncthreads();

    uint32_t n = min(g_cnt[row], (uint32_t)CAP);
    for (uint32_t j = threadIdx.x; j < n; j += 256) {
        uint32_t m = (uint32_t)(g_pairs[row][j] >> 18);
        atomicAdd(&hist2[(m - T_LO) >> 8], 1u);
    }
    __syncthreads();

    if (threadIdx.x == 0) {
        uint32_t r = (uint32_t)KKEEP - g_below[row];  // 1-indexed rank among candidates
        uint32_t cum = 0, B2 = 0;
        for (int b = 0; b < 1024; b++) {
            uint32_t h = hist2[b];
            if (cum + h >= r) { B2 = (uint32_t)b; break; }
            cum += h;
        }
        sB2 = B2; sR2 = r - cum;                      // 1-indexed within bucket
    }
    __syncthreads();

    uint32_t B2 = sB2, r2 = sR2;
    for (uint32_t j = threadIdx.x; j < n; j += 256) {
        unsigned long long v = g_pairs[row][j];
        uint32_t m = (uint32_t)(v >> 18);
        if (((m - T_LO) >> 8) == B2) {
            uint32_t pos = atomicAdd(&sn2, 1u);
            if (pos < 256u) sp2[pos] = v;
        }
    }
    __syncthreads();

    uint32_t n2 = min(sn2, 256u);
    for (uint32_t j = threadIdx.x; j < n2; j += 256) {
        unsigned long long v = sp2[j];
        uint32_t rk = 0;
        for (uint32_t l = 0; l < n2; l++) rk += (sp2[l] < v) ? 1u : 0u;
        if (rk == r2 - 1u) sT = (uint32_t)(v >> 18);
    }
    __syncthreads();

    uint32_t T = sT;
    if (threadIdx.x == 0) g_thresh[row] = T;
    for (uint32_t j = threadIdx.x; j < n2; j += 256) {
        unsigned long long v = sp2[j];
        if ((uint32_t)(v >> 18) == T) {
            uint32_t rk = 0;
            for (uint32_t l = 0; l < n2; l++) rk += (sp2[l] < v) ? 1u : 0u;
            if (rk < r2) {
                uint32_t pos = atomicAdd(&g_ntk[row], 1u);
                if (pos < 64u) g_tiecols[row][pos] = (uint32_t)(v & 0x3FFFFu);
            }
        }
    }
}

// Fused: per pixel-quad -> mask (write) + all 3 channels of out (2-way ILP noise)
__global__ void __launch_bounds__(256)
k_out_fused(const float4* __restrict__ x, float4* __restrict__ out,
            float4* __restrict__ maskout, uint32_t nk0, uint32_t nk1,
            uint4 pw0, uint4 pw1) {
    uint32_t q   = blockIdx.x * blockDim.x + threadIdx.x;  // [0, NU/4)
    uint32_t pix = q * 4u;
    uint32_t b   = pix >> 18;
    uint32_t p   = pix & 0x3FFFFu;
    uint32_t T   = g_thresh[b];
    uint32_t ks2 = nk0 ^ nk1 ^ 0x1BD11BDAu;

    uint4 mq = reinterpret_cast<const uint4*>(g_m)[q];
    uint32_t ms[4] = {mq.x, mq.y, mq.z, mq.w};
    float mk[4];
    bool anytie = (ms[0] == T) | (ms[1] == T) | (ms[2] == T) | (ms[3] == T);
#pragma unroll
    for (int j = 0; j < 4; j++) mk[j] = (ms[j] < T) ? 1.0f : 0.0f;
    if (anytie) {
        uint32_t ntk = g_ntk[b];
#pragma unroll
        for (int j = 0; j < 4; j++) {
            if (ms[j] == T) {
                uint32_t col = p + (uint32_t)j;
                for (uint32_t t = 0; t < ntk; t++)
                    if (g_tiecols[b][t] == col) mk[j] = 1.0f;
            }
        }
    }
    maskout[q] = make_float4(mk[0], mk[1], mk[2], mk[3]);

    uint32_t gibase = (b * 3u) * (uint32_t)HW + p;   // channel 0 element index
#pragma unroll
    for (int c = 0; c < 3; c++) {
        uint32_t gi = gibase + (uint32_t)c * (uint32_t)HW;
        float4 xv = x[gi >> 2];
        float n0, n1, n2, n3;
        noise2_f(nk0, nk1, ks2, gi + 0u, gi + 1u, pw0, pw1, n0, n1);
        noise2_f(nk0, nk1, ks2, gi + 2u, gi + 3u, pw0, pw1, n2, n3);
        float4 o;
        o.x = xv.x * mk[0] * n0;
        o.y = xv.y * mk[1] * n1;
        o.z = xv.z * mk[2] * n2;
        o.w = xv.w * mk[3] * n3;
        out[gi >> 2] = o;
    }
}

// ---------------- launch ------------------------------------------------------
extern "C" void kernel_launch(void* const* d_in, const int* in_sizes, int n_in,
                              void* d_out, int out_size) {
    const float* x   = (const float*)d_in[0];
    float* out       = (float*)d_out;
    float* maskout   = out + NX;          // output layout: [x (NX) | mask (NU)]

    // jax.random.key(42) -> (0,42); partitionable fold-like split:
    uint32_t mk0, mk1, nk0, nk1;
    tf2x32_h(0u, 42u, 0u, 0u, mk0, mk1);    // k_mask
    tf2x32_h(0u, 42u, 0u, 1u, nk0, nk1);    // k_noise

    // rotation powers, passed as runtime args so ptxas emits IMAD.WIDE
    uint4 pw0 = make_uint4(1u << 13, 1u << 15, 1u << 26, 1u << 6);
    uint4 pw1 = make_uint4(1u << 17, 1u << 29, 1u << 16, 1u << 24);

    k_init     <<<1, 64>>>();
    k_gen      <<<BSZ * SEG, 256>>>(mk0, mk1, pw0, pw1);
    k_sel      <<<BSZ, 256>>>();
    k_out_fused<<<(NU / 4) / 256, 256>>>((const float4*)x, (float4*)out,
                                         (float4*)maskout, nk0, nk1, pw0, pw1);
}